// round 13
// baseline (speedup 1.0000x reference)
#include <cuda_runtime.h>
#include <cuda_bf16.h>
#include <math.h>
#include <stdint.h>

#define BATCH 512
#define INCAPS 1152
#define OUTCAPS 10
#define INDIM 8
#define OUTDIM 16
#define EPSF 1e-8f

// ---- scratch (device globals; no allocations allowed) ----
__device__ float g_h2[BATCH * 256 * 36];             // conv2 out [B,256,6,6]
__device__ float g_u[BATCH * INCAPS * INDIM];        // squashed capsules [B,1152,8]
__device__ int   g_pred[BATCH];
__device__ float g_sel[BATCH * OUTDIM];
__device__ float g_cn[BATCH * OUTCAPS];              // per-(b,j) caps norm^2

// tensor-core conv2 operands (bf16 hi/lo split)
#define H1N (BATCH * 400 * 256)
#define W2N (256 * 20736)
__device__ __align__(256) __nv_bfloat16 g_h1hi[H1N];   // NHWC hi [b][pix][c]
__device__ __align__(256) __nv_bfloat16 g_h1lo[H1N];   // NHWC lo
__device__ __align__(256) __nv_bfloat16 g_w2hi[W2N];   // [chunk c][oc][64 ic]
__device__ __align__(256) __nv_bfloat16 g_w2lo[W2N];

// output layout (float32): caps | recon | pred
#define CAPS_OFF  0
#define RECON_OFF (BATCH * OUTCAPS * OUTDIM)              // 81920
#define PRED_OFF  (RECON_OFF + BATCH * 784)               // 483328

// ============================================================
// conv1 fused: x (*) w stride1 + bias, ReLU -> NHWC bf16 hi/lo directly.
// ============================================================
__global__ __launch_bounds__(256) void conv1_kernel(const float* __restrict__ x,
                                                    const float* __restrict__ w,
                                                    const float* __restrict__ bias) {
    __shared__ __align__(16) float img[784];
    __shared__ float wts[16 * 81];
    __shared__ float stage[16 * 401];
    int b = blockIdx.x, c0 = blockIdx.y * 16, t = threadIdx.x;
    for (int i = t; i < 784; i += 256) img[i] = x[b * 784 + i];
    for (int i = t; i < 16 * 81; i += 256) wts[i] = w[c0 * 81 + i];
    __syncthreads();
    for (int idx = t; idx < 1600; idx += 256) {
        int cl = idx / 100;
        int rem = idx % 100;
        int oy = rem / 5;
        int ox0 = (rem % 5) * 4;
        float bb = bias[c0 + cl];
        float a0 = bb, a1 = bb, a2 = bb, a3 = bb;
        const float* wp = &wts[cl * 81];
#pragma unroll
        for (int ky = 0; ky < 9; ky++) {
            const float4* ip = (const float4*)&img[(oy + ky) * 28 + ox0];
            float4 q0 = ip[0], q1 = ip[1], q2 = ip[2];
            float v[12] = {q0.x, q0.y, q0.z, q0.w, q1.x, q1.y, q1.z, q1.w,
                           q2.x, q2.y, q2.z, q2.w};
#pragma unroll
            for (int kx = 0; kx < 9; kx++) {
                float wv = wp[ky * 9 + kx];
                a0 += wv * v[kx];
                a1 += wv * v[kx + 1];
                a2 += wv * v[kx + 2];
                a3 += wv * v[kx + 3];
            }
        }
        float* sp = &stage[cl * 401 + oy * 20 + ox0];
        sp[0] = fmaxf(a0, 0.f);
        sp[1] = fmaxf(a1, 0.f);
        sp[2] = fmaxf(a2, 0.f);
        sp[3] = fmaxf(a3, 0.f);
    }
    __syncthreads();
    for (int p = t; p < 400; p += 256) {
        uint32_t hp[8], lp[8];
#pragma unroll
        for (int k = 0; k < 8; k++) {
            float v0 = stage[(2 * k) * 401 + p];
            float v1 = stage[(2 * k + 1) * 401 + p];
            __nv_bfloat16 h0 = __float2bfloat16(v0);
            __nv_bfloat16 h1 = __float2bfloat16(v1);
            float l0 = v0 - __bfloat162float(h0);
            float l1 = v1 - __bfloat162float(h1);
            __nv_bfloat16 lo0 = __float2bfloat16(l0);
            __nv_bfloat16 lo1 = __float2bfloat16(l1);
            hp[k] = (uint32_t)__bfloat16_as_ushort(h0) |
                    ((uint32_t)__bfloat16_as_ushort(h1) << 16);
            lp[k] = (uint32_t)__bfloat16_as_ushort(lo0) |
                    ((uint32_t)__bfloat16_as_ushort(lo1) << 16);
        }
        int off = (b * 400 + p) * 256 + c0;
        uint4* dh = (uint4*)(g_h1hi + off);
        uint4* dl = (uint4*)(g_h1lo + off);
        dh[0] = make_uint4(hp[0], hp[1], hp[2], hp[3]);
        dh[1] = make_uint4(hp[4], hp[5], hp[6], hp[7]);
        dl[0] = make_uint4(lp[0], lp[1], lp[2], lp[3]);
        dl[1] = make_uint4(lp[4], lp[5], lp[6], lp[7]);
    }
}

// ============================================================
// weight repack: c2w[oc][ic][81] fp32 -> [c=k*4+icc][oc][ici] bf16 hi/lo
// ============================================================
__global__ void repack_w2_kernel(const float* __restrict__ w) {
    int idx = blockIdx.x * 256 + threadIdx.x;
    if (idx >= W2N) return;
    int ici = idx & 63;
    int oc = (idx >> 6) & 255;
    int c = idx >> 14;           // 0..323
    int k = c >> 2, icc = c & 3;
    int ic = icc * 64 + ici;
    float v = w[(oc * 256 + ic) * 81 + k];
    __nv_bfloat16 hi = __float2bfloat16(v);
    float lo = v - __bfloat162float(hi);
    g_w2hi[idx] = hi;
    g_w2lo[idx] = __float2bfloat16(lo);
}

// ============================================================
// conv2 via HMMA (mma.sync m16n8k16 bf16): D[pos 128][oc 128] tiles.
// K = 81*256 in chunks of 64. hi/lo bf16 split (3 MMAs per step).
// (exact R7 code — known 3009us, rel_err 4.9e-5)
// ============================================================
#define NCHUNK 324
#define SMEM_STAGE 65536
#define SM_A(s) ((s) * SMEM_STAGE)          // Xhi 16K | Xlo 16K
#define SM_B(s) ((s) * SMEM_STAGE + 32768)  // Whi 16K | Wlo 16K
#define SMEM_BYTES (2 * SMEM_STAGE)
#define SWZ(x) ((x) ^ (((x) >> 3) & 0x70))

__device__ __forceinline__ uint32_t smem_u32(const void* p) {
    uint32_t a;
    asm("{ .reg .u64 t; cvta.to.shared.u64 t, %1; cvt.u32.u64 %0, t; }" : "=r"(a) : "l"(p));
    return a;
}
__device__ __forceinline__ void cp16(uint32_t dst, const void* src) {
    asm volatile("cp.async.cg.shared.global [%0], [%1], 16;" :: "r"(dst), "l"(src) : "memory");
}
#define LDMX4(r, addr)                                                          \
    asm volatile("ldmatrix.sync.aligned.m8n8.x4.shared.b16 {%0,%1,%2,%3}, [%4];" \
                 : "=r"((r)[0]), "=r"((r)[1]), "=r"((r)[2]), "=r"((r)[3])        \
                 : "r"(addr))
#define MMA(d, a, b0, b1)                                                        \
    asm volatile("mma.sync.aligned.m16n8k16.row.col.f32.bf16.bf16.f32 "          \
                 "{%0,%1,%2,%3}, {%4,%5,%6,%7}, {%8,%9}, {%0,%1,%2,%3};"         \
                 : "+f"((d)[0]), "+f"((d)[1]), "+f"((d)[2]), "+f"((d)[3])        \
                 : "r"((a)[0]), "r"((a)[1]), "r"((a)[2]), "r"((a)[3]),           \
                   "r"(b0), "r"(b1))

__global__ __launch_bounds__(256, 1) void conv2_mma_kernel(const float* __restrict__ bias) {
    extern __shared__ char cs[];
    uint32_t sb = smem_u32(cs);
    int tid = threadIdx.x;
    int wid = tid >> 5;
    int l = tid & 31;
    int o0 = blockIdx.y * 128;

    int seg = tid & 7;
    int r8 = tid >> 3;
    int abase[4];
#pragma unroll
    for (int q = 0; q < 4; q++) {
        int row = r8 + 32 * q;
        int pos = blockIdx.x * 128 + row;
        int b = pos / 36, s = pos % 36;
        int oy = s / 6, ox = s % 6;
        abase[q] = (b * 400 + oy * 40 + ox * 2) * 256 + seg * 8;
    }
    uint32_t ldst[4];
#pragma unroll
    for (int q = 0; q < 4; q++) ldst[q] = SWZ((r8 + 32 * q) * 128 + seg * 16);

    int mw = (wid & 1) * 64;
    int nw = (wid >> 1) * 32;
    int a_row = mw + (l & 7) + ((l >> 3) & 1) * 8;
    int a_kh = ((l >> 4) & 1) * 16;
    int xra = (a_row & 7) << 4;
    int b_row = nw + (l & 7) + ((l >> 4) & 1) * 8;
    int b_kh = ((l >> 3) & 1) * 16;
    int xrb = (b_row & 7) << 4;
    uint32_t arow128[4], brow128[2];
#pragma unroll
    for (int mt = 0; mt < 4; mt++) arow128[mt] = (a_row + mt * 16) * 128;
#pragma unroll
    for (int nt2 = 0; nt2 < 2; nt2++) brow128[nt2] = (b_row + nt2 * 16) * 128;

    float d[4][4][4];
#pragma unroll
    for (int mt = 0; mt < 4; mt++)
#pragma unroll
        for (int nt = 0; nt < 4; nt++)
#pragma unroll
            for (int r = 0; r < 4; r++) d[mt][nt][r] = 0.f;

    {
        uint32_t sA = sb + SM_A(0), sB = sb + SM_B(0);
#pragma unroll
        for (int q = 0; q < 4; q++) {
            cp16(sA + ldst[q], g_h1hi + abase[q]);
            cp16(sA + 16384 + ldst[q], g_h1lo + abase[q]);
        }
        int bs = (o0 + r8) * 64 + seg * 8;
#pragma unroll
        for (int q = 0; q < 4; q++) {
            cp16(sB + ldst[q], g_w2hi + bs + q * 2048);
            cp16(sB + 16384 + ldst[q], g_w2lo + bs + q * 2048);
        }
        asm volatile("cp.async.commit_group;" ::: "memory");
    }

    for (int i = 0; i < NCHUNK; i++) {
        int cur = i & 1;
        if (i + 1 < NCHUNK) {
            int c = i + 1;
            int k = c >> 2, ic0 = (c & 3) * 64;
            int aoff = ((k / 9) * 20 + (k % 9)) * 256 + ic0;
            uint32_t sA = sb + SM_A(cur ^ 1), sB = sb + SM_B(cur ^ 1);
#pragma unroll
            for (int q = 0; q < 4; q++) {
                cp16(sA + ldst[q], g_h1hi + abase[q] + aoff);
                cp16(sA + 16384 + ldst[q], g_h1lo + abase[q] + aoff);
            }
            int bs = c * 16384 + (o0 + r8) * 64 + seg * 8;
#pragma unroll
            for (int q = 0; q < 4; q++) {
                cp16(sB + ldst[q], g_w2hi + bs + q * 2048);
                cp16(sB + 16384 + ldst[q], g_w2lo + bs + q * 2048);
            }
            asm volatile("cp.async.commit_group;" ::: "memory");
            asm volatile("cp.async.wait_group 1;" ::: "memory");
        } else {
            asm volatile("cp.async.wait_group 0;" ::: "memory");
        }
        __syncthreads();

        uint32_t sAh = sb + SM_A(cur), sAl = sAh + 16384;
        uint32_t sBh = sb + SM_B(cur), sBl = sBh + 16384;
#pragma unroll
        for (int ks = 0; ks < 4; ks++) {
            uint32_t aH[4][4], aL[4][4], bH[2][4], bL[2][4];
            uint32_t offA = (uint32_t)((ks * 32 + a_kh) ^ xra);
            uint32_t offB = (uint32_t)((ks * 32 + b_kh) ^ xrb);
#pragma unroll
            for (int mt = 0; mt < 4; mt++) {
                LDMX4(aH[mt], sAh + arow128[mt] + offA);
                LDMX4(aL[mt], sAl + arow128[mt] + offA);
            }
#pragma unroll
            for (int nt2 = 0; nt2 < 2; nt2++) {
                LDMX4(bH[nt2], sBh + brow128[nt2] + offB);
                LDMX4(bL[nt2], sBl + brow128[nt2] + offB);
            }
#pragma unroll
            for (int mt = 0; mt < 4; mt++) {
#pragma unroll
                for (int nt = 0; nt < 4; nt++) {
                    int n2 = nt >> 1, se = (nt & 1) * 2;
                    MMA(d[mt][nt], aH[mt], bH[n2][se], bH[n2][se + 1]);
                    MMA(d[mt][nt], aH[mt], bL[n2][se], bL[n2][se + 1]);
                    MMA(d[mt][nt], aL[mt], bH[n2][se], bH[n2][se + 1]);
                }
            }
        }
        __syncthreads();
    }

    float bn[4][2];
#pragma unroll
    for (int nt = 0; nt < 4; nt++) {
        int n = o0 + nw + nt * 8 + (l & 3) * 2;
        bn[nt][0] = bias[n];
        bn[nt][1] = bias[n + 1];
    }
#pragma unroll
    for (int mt = 0; mt < 4; mt++) {
        int m0 = blockIdx.x * 128 + mw + mt * 16 + (l >> 2);
        int b0 = m0 / 36, s0 = m0 % 36;
        int m1 = m0 + 8;
        int b1 = m1 / 36, s1 = m1 % 36;
        int base0 = b0 * 9216 + s0;
        int base1 = b1 * 9216 + s1;
#pragma unroll
        for (int nt = 0; nt < 4; nt++) {
            int n = o0 + nw + nt * 8 + (l & 3) * 2;
            g_h2[base0 + n * 36]       = d[mt][nt][0] + bn[nt][0];
            g_h2[base0 + (n + 1) * 36] = d[mt][nt][1] + bn[nt][1];
            g_h2[base1 + n * 36]       = d[mt][nt][2] + bn[nt][0];
            g_h2[base1 + (n + 1) * 36] = d[mt][nt][3] + bn[nt][1];
        }
    }
}

// ============================================================
// capsule gather + squash: g_h2 -> g_u[B,1152,8]
// ============================================================
__global__ void usq_kernel() {
    int idx = blockIdx.x * 256 + threadIdx.x;
    if (idx >= BATCH * INCAPS) return;
    int b = idx / INCAPS, i = idx % INCAPS;
    int r = i / 36, s = i % 36;
    float v[8];
    float s2 = 0.f;
#pragma unroll
    for (int n = 0; n < 8; n++) {
        v[n] = g_h2[(b * 256 + n * 32 + r) * 36 + s];
        s2 += v[n] * v[n];
    }
    float scale = (s2 / (1.f + s2)) / sqrtf(s2 + EPSF);
#pragma unroll
    for (int n = 0; n < 8; n++) g_u[idx * 8 + n] = v[n] * scale;
}

// ============================================================
// fused uhat + routing, block = (2 batches, 1 out-capsule j).
// u_hat tile computed once into smem (stride-17 padded), 3 routing
// iterations run entirely from smem. W (5.9MB) stays L2-resident and
// is read once per block for 2 batches. g_uhat (377MB) eliminated.
// ============================================================
__device__ __forceinline__ float grp16_full(float v) {
#pragma unroll
    for (int o = 8; o > 0; o >>= 1) v += __shfl_xor_sync(0xffffffffu, v, o, 16);
    return v;
}
__device__ __forceinline__ float grp16_lo(float v) {
#pragma unroll
    for (int o = 8; o > 0; o >>= 1) v += __shfl_xor_sync(0x0000ffffu, v, o, 16);
    return v;
}

#define UHPAD 17
#define RT_SMEM (2 * INCAPS * UHPAD * 4)

__global__ __launch_bounds__(256) void route_kernel(const float* __restrict__ W,
                                                    float* __restrict__ out) {
    extern __shared__ float sm[];   // uh0[1152*17] | uh1[1152*17]
    __shared__ float red[2][8][16];
    __shared__ float redz[2][8];
    __shared__ float vsh[2][2][16];  // slot0 = v1, slot1 = v1+v2
    int t = threadIdx.x;
    int j = blockIdx.y;
    int b0 = blockIdx.x * 2;

    // ---- phase B: u_hat tiles for b0, b0+1 ----
    for (int idx = t; idx < INCAPS * 16; idx += 256) {
        int i = idx >> 4, m = idx & 15;
        const float* wrow = W + i * 1280 + j * 128 + m;
        const float* u0p = g_u + (b0 * INCAPS + i) * 8;
        const float* u1p = u0p + INCAPS * 8;
        float a0 = 0.f, a1 = 0.f;
#pragma unroll
        for (int n = 0; n < 8; n++) {
            float wv = wrow[n * 16];
            a0 += wv * u0p[n];
            a1 += wv * u1p[n];
        }
        sm[(idx >> 4) * UHPAD + m] = a0;                       // uh0
        sm[INCAPS * UHPAD + (idx >> 4) * UHPAD + m] = a1;      // uh1
    }
    __syncthreads();

    int tt = t >> 7;          // tile (batch) 0/1
    int lt = t & 127;
    int m = lt & 15;
    int g = lt >> 4;          // 0..7
    float* U = sm + tt * (INCAPS * UHPAD);

    // ---- iter 1: uniform c ----
    float p = 0.f;
    for (int i = g; i < INCAPS; i += 8) p += U[i * UHPAD + m];
    red[tt][g][m] = p;
    __syncthreads();
    if (g == 0) {
        float s = 0.f;
#pragma unroll
        for (int gg = 0; gg < 8; gg++) s += red[tt][gg][m];
        s *= (1.0f / 1152.0f);
        float n2 = grp16_lo(s * s);
        float v1 = s * (n2 / (1.f + n2)) / sqrtf(n2 + EPSF);
        vsh[tt][0][m] = v1;
    }
    __syncthreads();

    // ---- iter 2: weights exp(v1 . u_hat) ----
    float v1m = vsh[tt][0][m];
    float acc = 0.f, z = 0.f;
    for (int i = g; i < INCAPS; i += 8) {
        float u = U[i * UHPAD + m];
        float dd = grp16_full(v1m * u);
        float e = __expf(dd);
        acc += e * u;
        z += e;
    }
    __syncthreads();            // red reuse: prior reads done
    red[tt][g][m] = acc;
    if (m == 0) redz[tt][g] = z;
    __syncthreads();
    if (g == 0) {
        float sa = 0.f, sz = 0.f;
#pragma unroll
        for (int gg = 0; gg < 8; gg++) { sa += red[tt][gg][m]; sz += redz[tt][gg]; }
        float s = sa / sz;
        float n2 = grp16_lo(s * s);
        float v2 = s * (n2 / (1.f + n2)) / sqrtf(n2 + EPSF);
        vsh[tt][1][m] = vsh[tt][0][m] + v2;
    }
    __syncthreads();

    // ---- iter 3: weights exp((v1+v2) . u_hat) ----
    float w12 = vsh[tt][1][m];
    float acc3 = 0.f, z3 = 0.f;
    for (int i = g; i < INCAPS; i += 8) {
        float u = U[i * UHPAD + m];
        float dd = grp16_full(w12 * u);
        float e = __expf(dd);
        acc3 += e * u;
        z3 += e;
    }
    __syncthreads();
    red[tt][g][m] = acc3;
    if (m == 0) redz[tt][g] = z3;
    __syncthreads();
    if (g == 0) {
        float sa = 0.f, sz = 0.f;
#pragma unroll
        for (int gg = 0; gg < 8; gg++) { sa += red[tt][gg][m]; sz += redz[tt][gg]; }
        float s = sa / sz;
        float n2 = grp16_lo(s * s);
        float v3 = s * (n2 / (1.f + n2)) / sqrtf(n2 + EPSF);
        out[CAPS_OFF + (b0 + tt) * 160 + j * 16 + m] = v3;
        float c2 = grp16_lo(v3 * v3);
        if (m == 0) g_cn[(b0 + tt) * OUTCAPS + j] = c2;
    }
}

// ============================================================
// finalize: per-sample argmax over j, emit pred + selected capsule
// ============================================================
__global__ void finalize_kernel(float* __restrict__ out) {
    int b = blockIdx.x * 256 + threadIdx.x;
    if (b >= BATCH) return;
    int best = 0;
    float bv = g_cn[b * OUTCAPS];
#pragma unroll
    for (int jj = 1; jj < OUTCAPS; jj++) {
        float c = g_cn[b * OUTCAPS + jj];
        if (c > bv) { bv = c; best = jj; }
    }
    g_pred[b] = best;
    out[PRED_OFF + b] = (float)best;
#pragma unroll
    for (int m = 0; m < 16; m++)
        g_sel[b * 16 + m] = out[CAPS_OFF + b * 160 + best * 16 + m];
}

// ============================================================
// decoder
// ============================================================
__global__ __launch_bounds__(256) void decoder_kernel(const float* __restrict__ d1w,
                                                      const float* __restrict__ d1b,
                                                      const float* __restrict__ d2w,
                                                      const float* __restrict__ d2b,
                                                      const float* __restrict__ d3w,
                                                      const float* __restrict__ d3b,
                                                      float* __restrict__ out) {
    __shared__ float r1s[4 * 512];
    __shared__ float r2s[4 * 1024];
    __shared__ float sel[4 * 16];
    __shared__ int pr[4];
    int b0 = blockIdx.x * 4;
    int t = threadIdx.x;
    if (t < 64) sel[t] = g_sel[(b0 + (t >> 4)) * 16 + (t & 15)];
    if (t < 4) pr[t] = g_pred[b0 + t];
    __syncthreads();

    for (int idx = t; idx < 4 * 512; idx += 256) {
        int g = idx >> 9, o = idx & 511;
        const float* wrow = &d1w[(pr[g] * 16) * 512 + o];
        float a = d1b[o];
#pragma unroll
        for (int k = 0; k < 16; k++) a += sel[g * 16 + k] * wrow[k * 512];
        r1s[idx] = fmaxf(a, 0.f);
    }
    __syncthreads();

#pragma unroll
    for (int c = 0; c < 2; c++) {
        int o1 = c * 512 + t, o2 = o1 + 256;
        float a[4][2];
#pragma unroll
        for (int g = 0; g < 4; g++) { a[g][0] = d2b[o1]; a[g][1] = d2b[o2]; }
        for (int k = 0; k < 512; k++) {
            float w1 = d2w[k * 1024 + o1];
            float w2 = d2w[k * 1024 + o2];
#pragma unroll
            for (int g = 0; g < 4; g++) {
                float r = r1s[g * 512 + k];
                a[g][0] += r * w1;
                a[g][1] += r * w2;
            }
        }
#pragma unroll
        for (int g = 0; g < 4; g++) {
            r2s[g * 1024 + o1] = fmaxf(a[g][0], 0.f);
            r2s[g * 1024 + o2] = fmaxf(a[g][1], 0.f);
        }
    }
    __syncthreads();

#pragma unroll
    for (int c = 0; c < 2; c++) {
        int o1 = c * 512 + t, o2 = o1 + 256;
        bool ok1 = o1 < 784, ok2 = o2 < 784;
        float a[4][2];
#pragma unroll
        for (int g = 0; g < 4; g++) {
            a[g][0] = ok1 ? d3b[o1] : 0.f;
            a[g][1] = ok2 ? d3b[o2] : 0.f;
        }
        for (int k = 0; k < 1024; k++) {
            float w1 = ok1 ? d3w[k * 784 + o1] : 0.f;
            float w2 = ok2 ? d3w[k * 784 + o2] : 0.f;
#pragma unroll
            for (int g = 0; g < 4; g++) {
                float r = r2s[g * 1024 + k];
                a[g][0] += r * w1;
                a[g][1] += r * w2;
            }
        }
#pragma unroll
        for (int g = 0; g < 4; g++) {
            if (ok1) out[RECON_OFF + (b0 + g) * 784 + o1] = 1.f / (1.f + expf(-a[g][0]));
            if (ok2) out[RECON_OFF + (b0 + g) * 784 + o2] = 1.f / (1.f + expf(-a[g][1]));
        }
    }
}

// ============================================================
extern "C" void kernel_launch(void* const* d_in, const int* in_sizes, int n_in,
                              void* d_out, int out_size) {
    const float* x   = (const float*)d_in[0];
    const float* c1w = (const float*)d_in[1];
    const float* c1b = (const float*)d_in[2];
    const float* c2w = (const float*)d_in[3];
    const float* c2b = (const float*)d_in[4];
    const float* W   = (const float*)d_in[5];
    const float* d1w = (const float*)d_in[6];
    const float* d1b = (const float*)d_in[7];
    const float* d2w = (const float*)d_in[8];
    const float* d2b = (const float*)d_in[9];
    const float* d3w = (const float*)d_in[10];
    const float* d3b = (const float*)d_in[11];
    float* out = (float*)d_out;

    cudaFuncSetAttribute(conv2_mma_kernel,
                         cudaFuncAttributeMaxDynamicSharedMemorySize, SMEM_BYTES);
    cudaFuncSetAttribute(route_kernel,
                         cudaFuncAttributeMaxDynamicSharedMemorySize, RT_SMEM);

    conv1_kernel<<<dim3(512, 16), 256>>>(x, c1w, c1b);
    repack_w2_kernel<<<(W2N + 255) / 256, 256>>>(c2w);
    conv2_mma_kernel<<<dim3(144, 2), 256, SMEM_BYTES>>>(c2b);
    usq_kernel<<<(BATCH * INCAPS + 255) / 256, 256>>>();
    route_kernel<<<dim3(BATCH / 2, OUTCAPS), 256, RT_SMEM>>>(W, out);
    finalize_kernel<<<2, 256>>>(out);
    decoder_kernel<<<BATCH / 4, 256>>>(d1w, d1b, d2w, d2b, d3w, d3b, out);
}

// round 16
// speedup vs baseline: 1.2598x; 1.2598x over previous
#include <cuda_runtime.h>
#include <cuda_bf16.h>
#include <cuda_fp16.h>
#include <math.h>
#include <stdint.h>

#define BATCH 512
#define INCAPS 1152
#define OUTCAPS 10
#define INDIM 8
#define OUTDIM 16
#define EPSF 1e-8f

// ---- scratch (device globals; no allocations allowed) ----
__device__ float g_h2[BATCH * 256 * 36];             // conv2 out [B,256,6,6]
__device__ float g_u[BATCH * INCAPS * INDIM];        // squashed capsules [B,1152,8]
__device__ int   g_pred[BATCH];
__device__ float g_sel[BATCH * OUTDIM];
__device__ __align__(256) __half g_uhat_h[(long long)BATCH * INCAPS * OUTCAPS * OUTDIM]; // 188MB fp16

// tensor-core conv2 operands (bf16 hi/lo split)
#define H1N (BATCH * 400 * 256)
#define W2N (256 * 20736)
__device__ __align__(256) __nv_bfloat16 g_h1hi[H1N];   // NHWC hi [b][pix][c]
__device__ __align__(256) __nv_bfloat16 g_h1lo[H1N];   // NHWC lo
__device__ __align__(256) __nv_bfloat16 g_w2hi[W2N];   // [chunk c][oc][64 ic]
__device__ __align__(256) __nv_bfloat16 g_w2lo[W2N];

// output layout (float32): caps | recon | pred
#define CAPS_OFF  0
#define RECON_OFF (BATCH * OUTCAPS * OUTDIM)              // 81920
#define PRED_OFF  (RECON_OFF + BATCH * 784)               // 483328

// ============================================================
// conv1 fused: x (*) w stride1 + bias, ReLU -> NHWC bf16 hi/lo directly.
// ============================================================
__global__ __launch_bounds__(256) void conv1_kernel(const float* __restrict__ x,
                                                    const float* __restrict__ w,
                                                    const float* __restrict__ bias) {
    __shared__ __align__(16) float img[784];
    __shared__ float wts[16 * 81];
    __shared__ float stage[16 * 401];
    int b = blockIdx.x, c0 = blockIdx.y * 16, t = threadIdx.x;
    for (int i = t; i < 784; i += 256) img[i] = x[b * 784 + i];
    for (int i = t; i < 16 * 81; i += 256) wts[i] = w[c0 * 81 + i];
    __syncthreads();
    for (int idx = t; idx < 1600; idx += 256) {
        int cl = idx / 100;
        int rem = idx % 100;
        int oy = rem / 5;
        int ox0 = (rem % 5) * 4;
        float bb = bias[c0 + cl];
        float a0 = bb, a1 = bb, a2 = bb, a3 = bb;
        const float* wp = &wts[cl * 81];
#pragma unroll
        for (int ky = 0; ky < 9; ky++) {
            const float4* ip = (const float4*)&img[(oy + ky) * 28 + ox0];
            float4 q0 = ip[0], q1 = ip[1], q2 = ip[2];
            float v[12] = {q0.x, q0.y, q0.z, q0.w, q1.x, q1.y, q1.z, q1.w,
                           q2.x, q2.y, q2.z, q2.w};
#pragma unroll
            for (int kx = 0; kx < 9; kx++) {
                float wv = wp[ky * 9 + kx];
                a0 += wv * v[kx];
                a1 += wv * v[kx + 1];
                a2 += wv * v[kx + 2];
                a3 += wv * v[kx + 3];
            }
        }
        float* sp = &stage[cl * 401 + oy * 20 + ox0];
        sp[0] = fmaxf(a0, 0.f);
        sp[1] = fmaxf(a1, 0.f);
        sp[2] = fmaxf(a2, 0.f);
        sp[3] = fmaxf(a3, 0.f);
    }
    __syncthreads();
    for (int p = t; p < 400; p += 256) {
        uint32_t hp[8], lp[8];
#pragma unroll
        for (int k = 0; k < 8; k++) {
            float v0 = stage[(2 * k) * 401 + p];
            float v1 = stage[(2 * k + 1) * 401 + p];
            __nv_bfloat16 h0 = __float2bfloat16(v0);
            __nv_bfloat16 h1 = __float2bfloat16(v1);
            float l0 = v0 - __bfloat162float(h0);
            float l1 = v1 - __bfloat162float(h1);
            __nv_bfloat16 lo0 = __float2bfloat16(l0);
            __nv_bfloat16 lo1 = __float2bfloat16(l1);
            hp[k] = (uint32_t)__bfloat16_as_ushort(h0) |
                    ((uint32_t)__bfloat16_as_ushort(h1) << 16);
            lp[k] = (uint32_t)__bfloat16_as_ushort(lo0) |
                    ((uint32_t)__bfloat16_as_ushort(lo1) << 16);
        }
        int off = (b * 400 + p) * 256 + c0;
        uint4* dh = (uint4*)(g_h1hi + off);
        uint4* dl = (uint4*)(g_h1lo + off);
        dh[0] = make_uint4(hp[0], hp[1], hp[2], hp[3]);
        dh[1] = make_uint4(hp[4], hp[5], hp[6], hp[7]);
        dl[0] = make_uint4(lp[0], lp[1], lp[2], lp[3]);
        dl[1] = make_uint4(lp[4], lp[5], lp[6], lp[7]);
    }
}

// ============================================================
// weight repack: c2w[oc][ic][81] fp32 -> [c=k*4+icc][oc][ici] bf16 hi/lo
// ============================================================
__global__ void repack_w2_kernel(const float* __restrict__ w) {
    int idx = blockIdx.x * 256 + threadIdx.x;
    if (idx >= W2N) return;
    int ici = idx & 63;
    int oc = (idx >> 6) & 255;
    int c = idx >> 14;           // 0..323
    int k = c >> 2, icc = c & 3;
    int ic = icc * 64 + ici;
    float v = w[(oc * 256 + ic) * 81 + k];
    __nv_bfloat16 hi = __float2bfloat16(v);
    float lo = v - __bfloat162float(hi);
    g_w2hi[idx] = hi;
    g_w2lo[idx] = __float2bfloat16(lo);
}

// ============================================================
// conv2 via HMMA (mma.sync m16n8k16 bf16) — exact R7 code (3009us baseline)
// ============================================================
#define NCHUNK 324
#define SMEM_STAGE 65536
#define SM_A(s) ((s) * SMEM_STAGE)
#define SM_B(s) ((s) * SMEM_STAGE + 32768)
#define SMEM_BYTES (2 * SMEM_STAGE)
#define SWZ(x) ((x) ^ (((x) >> 3) & 0x70))

__device__ __forceinline__ uint32_t smem_u32(const void* p) {
    uint32_t a;
    asm("{ .reg .u64 t; cvta.to.shared.u64 t, %1; cvt.u32.u64 %0, t; }" : "=r"(a) : "l"(p));
    return a;
}
__device__ __forceinline__ void cp16(uint32_t dst, const void* src) {
    asm volatile("cp.async.cg.shared.global [%0], [%1], 16;" :: "r"(dst), "l"(src) : "memory");
}
#define LDMX4(r, addr)                                                          \
    asm volatile("ldmatrix.sync.aligned.m8n8.x4.shared.b16 {%0,%1,%2,%3}, [%4];" \
                 : "=r"((r)[0]), "=r"((r)[1]), "=r"((r)[2]), "=r"((r)[3])        \
                 : "r"(addr))
#define MMA(d, a, b0, b1)                                                        \
    asm volatile("mma.sync.aligned.m16n8k16.row.col.f32.bf16.bf16.f32 "          \
                 "{%0,%1,%2,%3}, {%4,%5,%6,%7}, {%8,%9}, {%0,%1,%2,%3};"         \
                 : "+f"((d)[0]), "+f"((d)[1]), "+f"((d)[2]), "+f"((d)[3])        \
                 : "r"((a)[0]), "r"((a)[1]), "r"((a)[2]), "r"((a)[3]),           \
                   "r"(b0), "r"(b1))

__global__ __launch_bounds__(256, 1) void conv2_mma_kernel(const float* __restrict__ bias) {
    extern __shared__ char cs[];
    uint32_t sb = smem_u32(cs);
    int tid = threadIdx.x;
    int wid = tid >> 5;
    int l = tid & 31;
    int o0 = blockIdx.y * 128;

    int seg = tid & 7;
    int r8 = tid >> 3;
    int abase[4];
#pragma unroll
    for (int q = 0; q < 4; q++) {
        int row = r8 + 32 * q;
        int pos = blockIdx.x * 128 + row;
        int b = pos / 36, s = pos % 36;
        int oy = s / 6, ox = s % 6;
        abase[q] = (b * 400 + oy * 40 + ox * 2) * 256 + seg * 8;
    }
    uint32_t ldst[4];
#pragma unroll
    for (int q = 0; q < 4; q++) ldst[q] = SWZ((r8 + 32 * q) * 128 + seg * 16);

    int mw = (wid & 1) * 64;
    int nw = (wid >> 1) * 32;
    int a_row = mw + (l & 7) + ((l >> 3) & 1) * 8;
    int a_kh = ((l >> 4) & 1) * 16;
    int xra = (a_row & 7) << 4;
    int b_row = nw + (l & 7) + ((l >> 4) & 1) * 8;
    int b_kh = ((l >> 3) & 1) * 16;
    int xrb = (b_row & 7) << 4;
    uint32_t arow128[4], brow128[2];
#pragma unroll
    for (int mt = 0; mt < 4; mt++) arow128[mt] = (a_row + mt * 16) * 128;
#pragma unroll
    for (int nt2 = 0; nt2 < 2; nt2++) brow128[nt2] = (b_row + nt2 * 16) * 128;

    float d[4][4][4];
#pragma unroll
    for (int mt = 0; mt < 4; mt++)
#pragma unroll
        for (int nt = 0; nt < 4; nt++)
#pragma unroll
            for (int r = 0; r < 4; r++) d[mt][nt][r] = 0.f;

    {
        uint32_t sA = sb + SM_A(0), sB = sb + SM_B(0);
#pragma unroll
        for (int q = 0; q < 4; q++) {
            cp16(sA + ldst[q], g_h1hi + abase[q]);
            cp16(sA + 16384 + ldst[q], g_h1lo + abase[q]);
        }
        int bs = (o0 + r8) * 64 + seg * 8;
#pragma unroll
        for (int q = 0; q < 4; q++) {
            cp16(sB + ldst[q], g_w2hi + bs + q * 2048);
            cp16(sB + 16384 + ldst[q], g_w2lo + bs + q * 2048);
        }
        asm volatile("cp.async.commit_group;" ::: "memory");
    }

    for (int i = 0; i < NCHUNK; i++) {
        int cur = i & 1;
        if (i + 1 < NCHUNK) {
            int c = i + 1;
            int k = c >> 2, ic0 = (c & 3) * 64;
            int aoff = ((k / 9) * 20 + (k % 9)) * 256 + ic0;
            uint32_t sA = sb + SM_A(cur ^ 1), sB = sb + SM_B(cur ^ 1);
#pragma unroll
            for (int q = 0; q < 4; q++) {
                cp16(sA + ldst[q], g_h1hi + abase[q] + aoff);
                cp16(sA + 16384 + ldst[q], g_h1lo + abase[q] + aoff);
            }
            int bs = c * 16384 + (o0 + r8) * 64 + seg * 8;
#pragma unroll
            for (int q = 0; q < 4; q++) {
                cp16(sB + ldst[q], g_w2hi + bs + q * 2048);
                cp16(sB + 16384 + ldst[q], g_w2lo + bs + q * 2048);
            }
            asm volatile("cp.async.commit_group;" ::: "memory");
            asm volatile("cp.async.wait_group 1;" ::: "memory");
        } else {
            asm volatile("cp.async.wait_group 0;" ::: "memory");
        }
        __syncthreads();

        uint32_t sAh = sb + SM_A(cur), sAl = sAh + 16384;
        uint32_t sBh = sb + SM_B(cur), sBl = sBh + 16384;
#pragma unroll
        for (int ks = 0; ks < 4; ks++) {
            uint32_t aH[4][4], aL[4][4], bH[2][4], bL[2][4];
            uint32_t offA = (uint32_t)((ks * 32 + a_kh) ^ xra);
            uint32_t offB = (uint32_t)((ks * 32 + b_kh) ^ xrb);
#pragma unroll
            for (int mt = 0; mt < 4; mt++) {
                LDMX4(aH[mt], sAh + arow128[mt] + offA);
                LDMX4(aL[mt], sAl + arow128[mt] + offA);
            }
#pragma unroll
            for (int nt2 = 0; nt2 < 2; nt2++) {
                LDMX4(bH[nt2], sBh + brow128[nt2] + offB);
                LDMX4(bL[nt2], sBl + brow128[nt2] + offB);
            }
#pragma unroll
            for (int mt = 0; mt < 4; mt++) {
#pragma unroll
                for (int nt = 0; nt < 4; nt++) {
                    int n2 = nt >> 1, se = (nt & 1) * 2;
                    MMA(d[mt][nt], aH[mt], bH[n2][se], bH[n2][se + 1]);
                    MMA(d[mt][nt], aH[mt], bL[n2][se], bL[n2][se + 1]);
                    MMA(d[mt][nt], aL[mt], bH[n2][se], bH[n2][se + 1]);
                }
            }
        }
        __syncthreads();
    }

    float bn[4][2];
#pragma unroll
    for (int nt = 0; nt < 4; nt++) {
        int n = o0 + nw + nt * 8 + (l & 3) * 2;
        bn[nt][0] = bias[n];
        bn[nt][1] = bias[n + 1];
    }
#pragma unroll
    for (int mt = 0; mt < 4; mt++) {
        int m0 = blockIdx.x * 128 + mw + mt * 16 + (l >> 2);
        int b0 = m0 / 36, s0 = m0 % 36;
        int m1 = m0 + 8;
        int b1 = m1 / 36, s1 = m1 % 36;
        int base0 = b0 * 9216 + s0;
        int base1 = b1 * 9216 + s1;
#pragma unroll
        for (int nt = 0; nt < 4; nt++) {
            int n = o0 + nw + nt * 8 + (l & 3) * 2;
            g_h2[base0 + n * 36]       = d[mt][nt][0] + bn[nt][0];
            g_h2[base0 + (n + 1) * 36] = d[mt][nt][1] + bn[nt][1];
            g_h2[base1 + n * 36]       = d[mt][nt][2] + bn[nt][0];
            g_h2[base1 + (n + 1) * 36] = d[mt][nt][3] + bn[nt][1];
        }
    }
}

// ============================================================
// capsule gather + squash: g_h2 -> g_u[B,1152,8]
// ============================================================
__global__ void usq_kernel() {
    int idx = blockIdx.x * 256 + threadIdx.x;
    if (idx >= BATCH * INCAPS) return;
    int b = idx / INCAPS, i = idx % INCAPS;
    int r = i / 36, s = i % 36;
    float v[8];
    float s2 = 0.f;
#pragma unroll
    for (int n = 0; n < 8; n++) {
        v[n] = g_h2[(b * 256 + n * 32 + r) * 36 + s];
        s2 += v[n] * v[n];
    }
    float scale = (s2 / (1.f + s2)) / sqrtf(s2 + EPSF);
#pragma unroll
    for (int n = 0; n < 8; n++) g_u[idx * 8 + n] = v[n] * scale;
}

// ============================================================
// u_hat[b,i,j,m] = sum_n W[i,j,n,m] * u[b,i,n]  -> fp16 storage (188MB)
// ============================================================
__global__ __launch_bounds__(160) void uhat_kernel(const float* __restrict__ W) {
    __shared__ __align__(16) float usm[BATCH * 8];
    int i = blockIdx.x;
    int t = threadIdx.x;
    int j = t >> 4, m = t & 15;
    float wreg[8];
#pragma unroll
    for (int n = 0; n < 8; n++) wreg[n] = W[i * 1280 + j * 128 + n * 16 + m];
    for (int idx = t; idx < BATCH * 8; idx += 160) {
        int bb = idx >> 3, n = idx & 7;
        usm[idx] = g_u[bb * (INCAPS * 8) + i * 8 + n];
    }
    __syncthreads();
    for (int bb = 0; bb < BATCH; bb++) {
        const float4* up = (const float4*)&usm[bb * 8];
        float4 u0 = up[0], u1 = up[1];
        float acc = wreg[0] * u0.x + wreg[1] * u0.y + wreg[2] * u0.z + wreg[3] * u0.w +
                    wreg[4] * u1.x + wreg[5] * u1.y + wreg[6] * u1.z + wreg[7] * u1.w;
        g_uhat_h[(long long)(bb * INCAPS + i) * 160 + t] = __float2half_rn(acc);
    }
}

// ============================================================
// routing, i-parallel: block = b (512 blocks, 320 threads), warp = j.
// Lane strides i by 32, loads one 32B u_hat row, in-register 16-dot +
// exp + accumulate. One butterfly reduction per pass (not per element).
// argmax/pred/sel finalized in-block.
// ============================================================
__device__ __forceinline__ void ld_row16(const __half* p, float* f) {
    uint4 q0 = *(const uint4*)p;
    uint4 q1 = *(const uint4*)(p + 8);
    const __half2* h0 = (const __half2*)&q0;
    const __half2* h1 = (const __half2*)&q1;
#pragma unroll
    for (int k = 0; k < 4; k++) {
        float2 a = __half22float2(h0[k]);
        f[2 * k] = a.x;
        f[2 * k + 1] = a.y;
        float2 b = __half22float2(h1[k]);
        f[8 + 2 * k] = b.x;
        f[8 + 2 * k + 1] = b.y;
    }
}

__global__ __launch_bounds__(320) void routing_kernel(float* __restrict__ out) {
    __shared__ float cns[OUTCAPS];
    __shared__ float vsm[OUTCAPS][16];
    __shared__ int bestsm;
    int b = blockIdx.x;
    int t = threadIdx.x;
    int j = t >> 5;
    int lane = t & 31;
    const __half* uh = g_uhat_h + (long long)b * INCAPS * 160 + j * 16;

    // ---- iter 1: uniform c ----
    float s[16];
#pragma unroll
    for (int m = 0; m < 16; m++) s[m] = 0.f;
    for (int i = lane; i < INCAPS; i += 32) {
        float u[16];
        ld_row16(uh + (long long)i * 160, u);
#pragma unroll
        for (int m = 0; m < 16; m++) s[m] += u[m];
    }
#pragma unroll
    for (int o = 16; o > 0; o >>= 1)
#pragma unroll
        for (int m = 0; m < 16; m++) s[m] += __shfl_xor_sync(0xffffffffu, s[m], o);
    float n2 = 0.f;
#pragma unroll
    for (int m = 0; m < 16; m++) { s[m] *= (1.0f / 1152.0f); n2 += s[m] * s[m]; }
    float sc = (n2 / (1.f + n2)) / sqrtf(n2 + EPSF);
    float v[16];
#pragma unroll
    for (int m = 0; m < 16; m++) v[m] = s[m] * sc;

    // ---- iter 2: weights exp(v1 . u_hat) ----
    float acc[16], z = 0.f;
#pragma unroll
    for (int m = 0; m < 16; m++) acc[m] = 0.f;
    for (int i = lane; i < INCAPS; i += 32) {
        float u[16];
        ld_row16(uh + (long long)i * 160, u);
        float dd = 0.f;
#pragma unroll
        for (int m = 0; m < 16; m++) dd += v[m] * u[m];
        float e = __expf(dd);
        z += e;
#pragma unroll
        for (int m = 0; m < 16; m++) acc[m] += e * u[m];
    }
#pragma unroll
    for (int o = 16; o > 0; o >>= 1) {
#pragma unroll
        for (int m = 0; m < 16; m++) acc[m] += __shfl_xor_sync(0xffffffffu, acc[m], o);
        z += __shfl_xor_sync(0xffffffffu, z, o);
    }
    float n2b = 0.f;
    float w12[16];
    {
        float inv = 1.f / z;
#pragma unroll
        for (int m = 0; m < 16; m++) { s[m] = acc[m] * inv; n2b += s[m] * s[m]; }
        float sc2 = (n2b / (1.f + n2b)) / sqrtf(n2b + EPSF);
#pragma unroll
        for (int m = 0; m < 16; m++) w12[m] = v[m] + s[m] * sc2;
    }

    // ---- iter 3: weights exp((v1+v2) . u_hat) ----
    float z3 = 0.f;
#pragma unroll
    for (int m = 0; m < 16; m++) acc[m] = 0.f;
    for (int i = lane; i < INCAPS; i += 32) {
        float u[16];
        ld_row16(uh + (long long)i * 160, u);
        float dd = 0.f;
#pragma unroll
        for (int m = 0; m < 16; m++) dd += w12[m] * u[m];
        float e = __expf(dd);
        z3 += e;
#pragma unroll
        for (int m = 0; m < 16; m++) acc[m] += e * u[m];
    }
#pragma unroll
    for (int o = 16; o > 0; o >>= 1) {
#pragma unroll
        for (int m = 0; m < 16; m++) acc[m] += __shfl_xor_sync(0xffffffffu, acc[m], o);
        z3 += __shfl_xor_sync(0xffffffffu, z3, o);
    }
    float cn = 0.f;
    {
        float inv = 1.f / z3;
        float n2c = 0.f;
#pragma unroll
        for (int m = 0; m < 16; m++) { s[m] = acc[m] * inv; n2c += s[m] * s[m]; }
        float sc3 = (n2c / (1.f + n2c)) / sqrtf(n2c + EPSF);
#pragma unroll
        for (int m = 0; m < 16; m++) { s[m] *= sc3; cn += s[m] * s[m]; }
    }
    if (lane == 0) {
#pragma unroll
        for (int m = 0; m < 16; m++) {
            vsm[j][m] = s[m];
            out[CAPS_OFF + b * 160 + j * 16 + m] = s[m];
        }
        cns[j] = cn;
    }
    __syncthreads();
    if (t == 0) {
        int best = 0;
        float bv = cns[0];
#pragma unroll
        for (int jj = 1; jj < OUTCAPS; jj++)
            if (cns[jj] > bv) { bv = cns[jj]; best = jj; }
        bestsm = best;
        g_pred[b] = best;
        out[PRED_OFF + b] = (float)best;
    }
    __syncthreads();
    if (t < 16) g_sel[b * 16 + t] = vsm[bestsm][t];
}

// ============================================================
// decoder
// ============================================================
__global__ __launch_bounds__(256) void decoder_kernel(const float* __restrict__ d1w,
                                                      const float* __restrict__ d1b,
                                                      const float* __restrict__ d2w,
                                                      const float* __restrict__ d2b,
                                                      const float* __restrict__ d3w,
                                                      const float* __restrict__ d3b,
                                                      float* __restrict__ out) {
    __shared__ float r1s[4 * 512];
    __shared__ float r2s[4 * 1024];
    __shared__ float sel[4 * 16];
    __shared__ int pr[4];
    int b0 = blockIdx.x * 4;
    int t = threadIdx.x;
    if (t < 64) sel[t] = g_sel[(b0 + (t >> 4)) * 16 + (t & 15)];
    if (t < 4) pr[t] = g_pred[b0 + t];
    __syncthreads();

    for (int idx = t; idx < 4 * 512; idx += 256) {
        int g = idx >> 9, o = idx & 511;
        const float* wrow = &d1w[(pr[g] * 16) * 512 + o];
        float a = d1b[o];
#pragma unroll
        for (int k = 0; k < 16; k++) a += sel[g * 16 + k] * wrow[k * 512];
        r1s[idx] = fmaxf(a, 0.f);
    }
    __syncthreads();

#pragma unroll
    for (int c = 0; c < 2; c++) {
        int o1 = c * 512 + t, o2 = o1 + 256;
        float a[4][2];
#pragma unroll
        for (int g = 0; g < 4; g++) { a[g][0] = d2b[o1]; a[g][1] = d2b[o2]; }
        for (int k = 0; k < 512; k++) {
            float w1 = d2w[k * 1024 + o1];
            float w2 = d2w[k * 1024 + o2];
#pragma unroll
            for (int g = 0; g < 4; g++) {
                float r = r1s[g * 512 + k];
                a[g][0] += r * w1;
                a[g][1] += r * w2;
            }
        }
#pragma unroll
        for (int g = 0; g < 4; g++) {
            r2s[g * 1024 + o1] = fmaxf(a[g][0], 0.f);
            r2s[g * 1024 + o2] = fmaxf(a[g][1], 0.f);
        }
    }
    __syncthreads();

#pragma unroll
    for (int c = 0; c < 2; c++) {
        int o1 = c * 512 + t, o2 = o1 + 256;
        bool ok1 = o1 < 784, ok2 = o2 < 784;
        float a[4][2];
#pragma unroll
        for (int g = 0; g < 4; g++) {
            a[g][0] = ok1 ? d3b[o1] : 0.f;
            a[g][1] = ok2 ? d3b[o2] : 0.f;
        }
        for (int k = 0; k < 1024; k++) {
            float w1 = ok1 ? d3w[k * 784 + o1] : 0.f;
            float w2 = ok2 ? d3w[k * 784 + o2] : 0.f;
#pragma unroll
            for (int g = 0; g < 4; g++) {
                float r = r2s[g * 1024 + k];
                a[g][0] += r * w1;
                a[g][1] += r * w2;
            }
        }
#pragma unroll
        for (int g = 0; g < 4; g++) {
            if (ok1) out[RECON_OFF + (b0 + g) * 784 + o1] = 1.f / (1.f + expf(-a[g][0]));
            if (ok2) out[RECON_OFF + (b0 + g) * 784 + o2] = 1.f / (1.f + expf(-a[g][1]));
        }
    }
}

// ============================================================
extern "C" void kernel_launch(void* const* d_in, const int* in_sizes, int n_in,
                              void* d_out, int out_size) {
    const float* x   = (const float*)d_in[0];
    const float* c1w = (const float*)d_in[1];
    const float* c1b = (const float*)d_in[2];
    const float* c2w = (const float*)d_in[3];
    const float* c2b = (const float*)d_in[4];
    const float* W   = (const float*)d_in[5];
    const float* d1w = (const float*)d_in[6];
    const float* d1b = (const float*)d_in[7];
    const float* d2w = (const float*)d_in[8];
    const float* d2b = (const float*)d_in[9];
    const float* d3w = (const float*)d_in[10];
    const float* d3b = (const float*)d_in[11];
    float* out = (float*)d_out;

    cudaFuncSetAttribute(conv2_mma_kernel,
                         cudaFuncAttributeMaxDynamicSharedMemorySize, SMEM_BYTES);

    conv1_kernel<<<dim3(512, 16), 256>>>(x, c1w, c1b);
    repack_w2_kernel<<<(W2N + 255) / 256, 256>>>(c2w);
    conv2_mma_kernel<<<dim3(144, 2), 256, SMEM_BYTES>>>(c2b);
    usq_kernel<<<(BATCH * INCAPS + 255) / 256, 256>>>();
    uhat_kernel<<<INCAPS, 160>>>(W);
    routing_kernel<<<BATCH, 320>>>(out);
    decoder_kernel<<<BATCH / 4, 256>>>(d1w, d1b, d2w, d2b, d3w, d3b, out);
}

// round 17
// speedup vs baseline: 1.2619x; 1.0017x over previous
#include <cuda_runtime.h>
#include <cuda_bf16.h>
#include <cuda_fp16.h>
#include <math.h>
#include <stdint.h>

#define BATCH 512
#define INCAPS 1152
#define OUTCAPS 10
#define INDIM 8
#define OUTDIM 16
#define EPSF 1e-8f

// ---- scratch (device globals; no allocations allowed) ----
__device__ float g_h2[BATCH * 256 * 36];             // conv2 out [B,256,6,6]
__device__ float g_u[BATCH * INCAPS * INDIM];        // squashed capsules [B,1152,8]
__device__ int   g_pred[BATCH];
__device__ float g_sel[BATCH * OUTDIM];
__device__ __align__(256) __half g_uhat_h[(long long)BATCH * INCAPS * OUTCAPS * OUTDIM]; // 188MB fp16

// tensor-core conv2 operands (bf16 hi/lo split)
#define H1N (BATCH * 400 * 256)
#define W2N (256 * 20736)
__device__ __align__(256) __nv_bfloat16 g_h1hi[H1N];   // NHWC hi [b][pix][c]
__device__ __align__(256) __nv_bfloat16 g_h1lo[H1N];   // NHWC lo
__device__ __align__(256) __nv_bfloat16 g_w2hi[W2N];   // [chunk c][oc][64 ic]
__device__ __align__(256) __nv_bfloat16 g_w2lo[W2N];

// output layout (float32): caps | recon | pred
#define CAPS_OFF  0
#define RECON_OFF (BATCH * OUTCAPS * OUTDIM)              // 81920
#define PRED_OFF  (RECON_OFF + BATCH * 784)               // 483328

// ============================================================
// conv1 fused: x (*) w stride1 + bias, ReLU -> NHWC bf16 hi/lo directly.
// ============================================================
__global__ __launch_bounds__(256) void conv1_kernel(const float* __restrict__ x,
                                                    const float* __restrict__ w,
                                                    const float* __restrict__ bias) {
    __shared__ __align__(16) float img[784];
    __shared__ float wts[16 * 81];
    __shared__ float stage[16 * 401];
    int b = blockIdx.x, c0 = blockIdx.y * 16, t = threadIdx.x;
    for (int i = t; i < 784; i += 256) img[i] = x[b * 784 + i];
    for (int i = t; i < 16 * 81; i += 256) wts[i] = w[c0 * 81 + i];
    __syncthreads();
    for (int idx = t; idx < 1600; idx += 256) {
        int cl = idx / 100;
        int rem = idx % 100;
        int oy = rem / 5;
        int ox0 = (rem % 5) * 4;
        float bb = bias[c0 + cl];
        float a0 = bb, a1 = bb, a2 = bb, a3 = bb;
        const float* wp = &wts[cl * 81];
#pragma unroll
        for (int ky = 0; ky < 9; ky++) {
            const float4* ip = (const float4*)&img[(oy + ky) * 28 + ox0];
            float4 q0 = ip[0], q1 = ip[1], q2 = ip[2];
            float v[12] = {q0.x, q0.y, q0.z, q0.w, q1.x, q1.y, q1.z, q1.w,
                           q2.x, q2.y, q2.z, q2.w};
#pragma unroll
            for (int kx = 0; kx < 9; kx++) {
                float wv = wp[ky * 9 + kx];
                a0 += wv * v[kx];
                a1 += wv * v[kx + 1];
                a2 += wv * v[kx + 2];
                a3 += wv * v[kx + 3];
            }
        }
        float* sp = &stage[cl * 401 + oy * 20 + ox0];
        sp[0] = fmaxf(a0, 0.f);
        sp[1] = fmaxf(a1, 0.f);
        sp[2] = fmaxf(a2, 0.f);
        sp[3] = fmaxf(a3, 0.f);
    }
    __syncthreads();
    for (int p = t; p < 400; p += 256) {
        uint32_t hp[8], lp[8];
#pragma unroll
        for (int k = 0; k < 8; k++) {
            float v0 = stage[(2 * k) * 401 + p];
            float v1 = stage[(2 * k + 1) * 401 + p];
            __nv_bfloat16 h0 = __float2bfloat16(v0);
            __nv_bfloat16 h1 = __float2bfloat16(v1);
            float l0 = v0 - __bfloat162float(h0);
            float l1 = v1 - __bfloat162float(h1);
            __nv_bfloat16 lo0 = __float2bfloat16(l0);
            __nv_bfloat16 lo1 = __float2bfloat16(l1);
            hp[k] = (uint32_t)__bfloat16_as_ushort(h0) |
                    ((uint32_t)__bfloat16_as_ushort(h1) << 16);
            lp[k] = (uint32_t)__bfloat16_as_ushort(lo0) |
                    ((uint32_t)__bfloat16_as_ushort(lo1) << 16);
        }
        int off = (b * 400 + p) * 256 + c0;
        uint4* dh = (uint4*)(g_h1hi + off);
        uint4* dl = (uint4*)(g_h1lo + off);
        dh[0] = make_uint4(hp[0], hp[1], hp[2], hp[3]);
        dh[1] = make_uint4(hp[4], hp[5], hp[6], hp[7]);
        dl[0] = make_uint4(lp[0], lp[1], lp[2], lp[3]);
        dl[1] = make_uint4(lp[4], lp[5], lp[6], lp[7]);
    }
}

// ============================================================
// weight repack: c2w[oc][ic][81] fp32 -> [c=k*4+icc][oc][ici] bf16 hi/lo
// ============================================================
__global__ void repack_w2_kernel(const float* __restrict__ w) {
    int idx = blockIdx.x * 256 + threadIdx.x;
    if (idx >= W2N) return;
    int ici = idx & 63;
    int oc = (idx >> 6) & 255;
    int c = idx >> 14;           // 0..323
    int k = c >> 2, icc = c & 3;
    int ic = icc * 64 + ici;
    float v = w[(oc * 256 + ic) * 81 + k];
    __nv_bfloat16 hi = __float2bfloat16(v);
    float lo = v - __bfloat162float(hi);
    g_w2hi[idx] = hi;
    g_w2lo[idx] = __float2bfloat16(lo);
}

// ============================================================
// conv2 via HMMA: D[pos 128][oc 64] tiles (N halved so 2 CTAs/SM fit:
// 48KB/stage * 2 stages = 96KB/CTA, 192KB/SM). Fills the 25% tensor-idle
// barrier gaps with the co-resident CTA's MMAs.
// ============================================================
#define NCHUNK 324
#define SMEM_STAGE 49152
#define SM_A(s) ((s) * SMEM_STAGE)          // Xhi 16K | Xlo 16K
#define SM_B(s) ((s) * SMEM_STAGE + 32768)  // Whi 8K | Wlo 8K
#define SMEM_BYTES (2 * SMEM_STAGE)
#define SWZ(x) ((x) ^ (((x) >> 3) & 0x70))

__device__ __forceinline__ uint32_t smem_u32(const void* p) {
    uint32_t a;
    asm("{ .reg .u64 t; cvta.to.shared.u64 t, %1; cvt.u32.u64 %0, t; }" : "=r"(a) : "l"(p));
    return a;
}
__device__ __forceinline__ void cp16(uint32_t dst, const void* src) {
    asm volatile("cp.async.cg.shared.global [%0], [%1], 16;" :: "r"(dst), "l"(src) : "memory");
}
#define LDMX4(r, addr)                                                          \
    asm volatile("ldmatrix.sync.aligned.m8n8.x4.shared.b16 {%0,%1,%2,%3}, [%4];" \
                 : "=r"((r)[0]), "=r"((r)[1]), "=r"((r)[2]), "=r"((r)[3])        \
                 : "r"(addr))
#define MMA(d, a, b0, b1)                                                        \
    asm volatile("mma.sync.aligned.m16n8k16.row.col.f32.bf16.bf16.f32 "          \
                 "{%0,%1,%2,%3}, {%4,%5,%6,%7}, {%8,%9}, {%0,%1,%2,%3};"         \
                 : "+f"((d)[0]), "+f"((d)[1]), "+f"((d)[2]), "+f"((d)[3])        \
                 : "r"((a)[0]), "r"((a)[1]), "r"((a)[2]), "r"((a)[3]),           \
                   "r"(b0), "r"(b1))

__global__ __launch_bounds__(256, 2) void conv2_mma_kernel(const float* __restrict__ bias) {
    extern __shared__ char cs[];
    uint32_t sb = smem_u32(cs);
    int tid = threadIdx.x;
    int wid = tid >> 5;
    int l = tid & 31;
    int o0 = blockIdx.y * 64;

    // ---- load geometry ----
    int seg = tid & 7;
    int r8 = tid >> 3;           // 0..31
    int abase[4];
#pragma unroll
    for (int q = 0; q < 4; q++) {
        int row = r8 + 32 * q;
        int pos = blockIdx.x * 128 + row;
        int b = pos / 36, s = pos % 36;
        int oy = s / 6, ox = s % 6;
        abase[q] = (b * 400 + oy * 40 + ox * 2) * 256 + seg * 8;
    }
    uint32_t ldst[4];
#pragma unroll
    for (int q = 0; q < 4; q++) ldst[q] = SWZ((r8 + 32 * q) * 128 + seg * 16);

    // ---- compute geometry: 8 warps = 4(m) x 2(n), warp tile 32x32 ----
    int mw = (wid & 3) * 32;
    int nw = (wid >> 2) * 32;
    int a_row = mw + (l & 7) + ((l >> 3) & 1) * 8;
    int a_kh = ((l >> 4) & 1) * 16;
    int xra = (a_row & 7) << 4;
    int b_row = nw + (l & 7) + ((l >> 4) & 1) * 8;
    int b_kh = ((l >> 3) & 1) * 16;
    int xrb = (b_row & 7) << 4;
    uint32_t arow128[2], brow128[2];
#pragma unroll
    for (int mt = 0; mt < 2; mt++) arow128[mt] = (a_row + mt * 16) * 128;
#pragma unroll
    for (int nt2 = 0; nt2 < 2; nt2++) brow128[nt2] = (b_row + nt2 * 16) * 128;

    float d[2][4][4];
#pragma unroll
    for (int mt = 0; mt < 2; mt++)
#pragma unroll
        for (int nt = 0; nt < 4; nt++)
#pragma unroll
            for (int r = 0; r < 4; r++) d[mt][nt][r] = 0.f;

    // ---- preload chunk 0 ----
    {
        uint32_t sA = sb + SM_A(0), sB = sb + SM_B(0);
#pragma unroll
        for (int q = 0; q < 4; q++) {
            cp16(sA + ldst[q], g_h1hi + abase[q]);
            cp16(sA + 16384 + ldst[q], g_h1lo + abase[q]);
        }
        int bs = (o0 + r8) * 64 + seg * 8;
#pragma unroll
        for (int q = 0; q < 2; q++) {
            cp16(sB + ldst[q], g_w2hi + bs + q * 2048);
            cp16(sB + 8192 + ldst[q], g_w2lo + bs + q * 2048);
        }
        asm volatile("cp.async.commit_group;" ::: "memory");
    }

    for (int i = 0; i < NCHUNK; i++) {
        int cur = i & 1;
        if (i + 1 < NCHUNK) {
            int c = i + 1;
            int k = c >> 2, ic0 = (c & 3) * 64;
            int aoff = ((k / 9) * 20 + (k % 9)) * 256 + ic0;
            uint32_t sA = sb + SM_A(cur ^ 1), sB = sb + SM_B(cur ^ 1);
#pragma unroll
            for (int q = 0; q < 4; q++) {
                cp16(sA + ldst[q], g_h1hi + abase[q] + aoff);
                cp16(sA + 16384 + ldst[q], g_h1lo + abase[q] + aoff);
            }
            int bs = c * 16384 + (o0 + r8) * 64 + seg * 8;
#pragma unroll
            for (int q = 0; q < 2; q++) {
                cp16(sB + ldst[q], g_w2hi + bs + q * 2048);
                cp16(sB + 8192 + ldst[q], g_w2lo + bs + q * 2048);
            }
            asm volatile("cp.async.commit_group;" ::: "memory");
            asm volatile("cp.async.wait_group 1;" ::: "memory");
        } else {
            asm volatile("cp.async.wait_group 0;" ::: "memory");
        }
        __syncthreads();

        uint32_t sAh = sb + SM_A(cur), sAl = sAh + 16384;
        uint32_t sBh = sb + SM_B(cur), sBl = sBh + 8192;
#pragma unroll
        for (int ks = 0; ks < 4; ks++) {
            uint32_t aH[2][4], aL[2][4], bH[2][4], bL[2][4];
            uint32_t offA = (uint32_t)((ks * 32 + a_kh) ^ xra);
            uint32_t offB = (uint32_t)((ks * 32 + b_kh) ^ xrb);
#pragma unroll
            for (int mt = 0; mt < 2; mt++) {
                LDMX4(aH[mt], sAh + arow128[mt] + offA);
                LDMX4(aL[mt], sAl + arow128[mt] + offA);
            }
#pragma unroll
            for (int nt2 = 0; nt2 < 2; nt2++) {
                LDMX4(bH[nt2], sBh + brow128[nt2] + offB);
                LDMX4(bL[nt2], sBl + brow128[nt2] + offB);
            }
#pragma unroll
            for (int mt = 0; mt < 2; mt++) {
#pragma unroll
                for (int nt = 0; nt < 4; nt++) {
                    int n2 = nt >> 1, se = (nt & 1) * 2;
                    MMA(d[mt][nt], aH[mt], bH[n2][se], bH[n2][se + 1]);
                    MMA(d[mt][nt], aH[mt], bL[n2][se], bL[n2][se + 1]);
                    MMA(d[mt][nt], aL[mt], bH[n2][se], bH[n2][se + 1]);
                }
            }
        }
        __syncthreads();
    }

    // ---- epilogue: scatter to g_h2 [b][oc][36] with bias ----
    float bn[4][2];
#pragma unroll
    for (int nt = 0; nt < 4; nt++) {
        int n = o0 + nw + nt * 8 + (l & 3) * 2;
        bn[nt][0] = bias[n];
        bn[nt][1] = bias[n + 1];
    }
#pragma unroll
    for (int mt = 0; mt < 2; mt++) {
        int m0 = blockIdx.x * 128 + mw + mt * 16 + (l >> 2);
        int b0 = m0 / 36, s0 = m0 % 36;
        int m1 = m0 + 8;
        int b1 = m1 / 36, s1 = m1 % 36;
        int base0 = b0 * 9216 + s0;
        int base1 = b1 * 9216 + s1;
#pragma unroll
        for (int nt = 0; nt < 4; nt++) {
            int n = o0 + nw + nt * 8 + (l & 3) * 2;
            g_h2[base0 + n * 36]       = d[mt][nt][0] + bn[nt][0];
            g_h2[base0 + (n + 1) * 36] = d[mt][nt][1] + bn[nt][1];
            g_h2[base1 + n * 36]       = d[mt][nt][2] + bn[nt][0];
            g_h2[base1 + (n + 1) * 36] = d[mt][nt][3] + bn[nt][1];
        }
    }
}

// ============================================================
// capsule gather + squash: g_h2 -> g_u[B,1152,8]
// ============================================================
__global__ void usq_kernel() {
    int idx = blockIdx.x * 256 + threadIdx.x;
    if (idx >= BATCH * INCAPS) return;
    int b = idx / INCAPS, i = idx % INCAPS;
    int r = i / 36, s = i % 36;
    float v[8];
    float s2 = 0.f;
#pragma unroll
    for (int n = 0; n < 8; n++) {
        v[n] = g_h2[(b * 256 + n * 32 + r) * 36 + s];
        s2 += v[n] * v[n];
    }
    float scale = (s2 / (1.f + s2)) / sqrtf(s2 + EPSF);
#pragma unroll
    for (int n = 0; n < 8; n++) g_u[idx * 8 + n] = v[n] * scale;
}

// ============================================================
// u_hat[b,i,j,m] = sum_n W[i,j,n,m] * u[b,i,n]  -> fp16 storage (188MB)
// ============================================================
__global__ __launch_bounds__(160) void uhat_kernel(const float* __restrict__ W) {
    __shared__ __align__(16) float usm[BATCH * 8];
    int i = blockIdx.x;
    int t = threadIdx.x;
    int j = t >> 4, m = t & 15;
    float wreg[8];
#pragma unroll
    for (int n = 0; n < 8; n++) wreg[n] = W[i * 1280 + j * 128 + n * 16 + m];
    for (int idx = t; idx < BATCH * 8; idx += 160) {
        int bb = idx >> 3, n = idx & 7;
        usm[idx] = g_u[bb * (INCAPS * 8) + i * 8 + n];
    }
    __syncthreads();
    for (int bb = 0; bb < BATCH; bb++) {
        const float4* up = (const float4*)&usm[bb * 8];
        float4 u0 = up[0], u1 = up[1];
        float acc = wreg[0] * u0.x + wreg[1] * u0.y + wreg[2] * u0.z + wreg[3] * u0.w +
                    wreg[4] * u1.x + wreg[5] * u1.y + wreg[6] * u1.z + wreg[7] * u1.w;
        g_uhat_h[(long long)(bb * INCAPS + i) * 160 + t] = __float2half_rn(acc);
    }
}

// ============================================================
// routing, i-parallel: block = b (512 blocks, 320 threads), warp = j.
// ============================================================
__device__ __forceinline__ void ld_row16(const __half* p, float* f) {
    uint4 q0 = *(const uint4*)p;
    uint4 q1 = *(const uint4*)(p + 8);
    const __half2* h0 = (const __half2*)&q0;
    const __half2* h1 = (const __half2*)&q1;
#pragma unroll
    for (int k = 0; k < 4; k++) {
        float2 a = __half22float2(h0[k]);
        f[2 * k] = a.x;
        f[2 * k + 1] = a.y;
        float2 b = __half22float2(h1[k]);
        f[8 + 2 * k] = b.x;
        f[8 + 2 * k + 1] = b.y;
    }
}

__global__ __launch_bounds__(320) void routing_kernel(float* __restrict__ out) {
    __shared__ float cns[OUTCAPS];
    __shared__ float vsm[OUTCAPS][16];
    __shared__ int bestsm;
    int b = blockIdx.x;
    int t = threadIdx.x;
    int j = t >> 5;
    int lane = t & 31;
    const __half* uh = g_uhat_h + (long long)b * INCAPS * 160 + j * 16;

    // ---- iter 1 ----
    float s[16];
#pragma unroll
    for (int m = 0; m < 16; m++) s[m] = 0.f;
    for (int i = lane; i < INCAPS; i += 32) {
        float u[16];
        ld_row16(uh + (long long)i * 160, u);
#pragma unroll
        for (int m = 0; m < 16; m++) s[m] += u[m];
    }
#pragma unroll
    for (int o = 16; o > 0; o >>= 1)
#pragma unroll
        for (int m = 0; m < 16; m++) s[m] += __shfl_xor_sync(0xffffffffu, s[m], o);
    float n2 = 0.f;
#pragma unroll
    for (int m = 0; m < 16; m++) { s[m] *= (1.0f / 1152.0f); n2 += s[m] * s[m]; }
    float sc = (n2 / (1.f + n2)) / sqrtf(n2 + EPSF);
    float v[16];
#pragma unroll
    for (int m = 0; m < 16; m++) v[m] = s[m] * sc;

    // ---- iter 2 ----
    float acc[16], z = 0.f;
#pragma unroll
    for (int m = 0; m < 16; m++) acc[m] = 0.f;
    for (int i = lane; i < INCAPS; i += 32) {
        float u[16];
        ld_row16(uh + (long long)i * 160, u);
        float dd = 0.f;
#pragma unroll
        for (int m = 0; m < 16; m++) dd += v[m] * u[m];
        float e = __expf(dd);
        z += e;
#pragma unroll
        for (int m = 0; m < 16; m++) acc[m] += e * u[m];
    }
#pragma unroll
    for (int o = 16; o > 0; o >>= 1) {
#pragma unroll
        for (int m = 0; m < 16; m++) acc[m] += __shfl_xor_sync(0xffffffffu, acc[m], o);
        z += __shfl_xor_sync(0xffffffffu, z, o);
    }
    float n2b = 0.f;
    float w12[16];
    {
        float inv = 1.f / z;
#pragma unroll
        for (int m = 0; m < 16; m++) { s[m] = acc[m] * inv; n2b += s[m] * s[m]; }
        float sc2 = (n2b / (1.f + n2b)) / sqrtf(n2b + EPSF);
#pragma unroll
        for (int m = 0; m < 16; m++) w12[m] = v[m] + s[m] * sc2;
    }

    // ---- iter 3 ----
    float z3 = 0.f;
#pragma unroll
    for (int m = 0; m < 16; m++) acc[m] = 0.f;
    for (int i = lane; i < INCAPS; i += 32) {
        float u[16];
        ld_row16(uh + (long long)i * 160, u);
        float dd = 0.f;
#pragma unroll
        for (int m = 0; m < 16; m++) dd += w12[m] * u[m];
        float e = __expf(dd);
        z3 += e;
#pragma unroll
        for (int m = 0; m < 16; m++) acc[m] += e * u[m];
    }
#pragma unroll
    for (int o = 16; o > 0; o >>= 1) {
#pragma unroll
        for (int m = 0; m < 16; m++) acc[m] += __shfl_xor_sync(0xffffffffu, acc[m], o);
        z3 += __shfl_xor_sync(0xffffffffu, z3, o);
    }
    float cn = 0.f;
    {
        float inv = 1.f / z3;
        float n2c = 0.f;
#pragma unroll
        for (int m = 0; m < 16; m++) { s[m] = acc[m] * inv; n2c += s[m] * s[m]; }
        float sc3 = (n2c / (1.f + n2c)) / sqrtf(n2c + EPSF);
#pragma unroll
        for (int m = 0; m < 16; m++) { s[m] *= sc3; cn += s[m] * s[m]; }
    }
    if (lane == 0) {
#pragma unroll
        for (int m = 0; m < 16; m++) {
            vsm[j][m] = s[m];
            out[CAPS_OFF + b * 160 + j * 16 + m] = s[m];
        }
        cns[j] = cn;
    }
    __syncthreads();
    if (t == 0) {
        int best = 0;
        float bv = cns[0];
#pragma unroll
        for (int jj = 1; jj < OUTCAPS; jj++)
            if (cns[jj] > bv) { bv = cns[jj]; best = jj; }
        bestsm = best;
        g_pred[b] = best;
        out[PRED_OFF + b] = (float)best;
    }
    __syncthreads();
    if (t < 16) g_sel[b * 16 + t] = vsm[bestsm][t];
}

// ============================================================
// decoder
// ============================================================
__global__ __launch_bounds__(256) void decoder_kernel(const float* __restrict__ d1w,
                                                      const float* __restrict__ d1b,
                                                      const float* __restrict__ d2w,
                                                      const float* __restrict__ d2b,
                                                      const float* __restrict__ d3w,
                                                      const float* __restrict__ d3b,
                                                      float* __restrict__ out) {
    __shared__ float r1s[4 * 512];
    __shared__ float r2s[4 * 1024];
    __shared__ float sel[4 * 16];
    __shared__ int pr[4];
    int b0 = blockIdx.x * 4;
    int t = threadIdx.x;
    if (t < 64) sel[t] = g_sel[(b0 + (t >> 4)) * 16 + (t & 15)];
    if (t < 4) pr[t] = g_pred[b0 + t];
    __syncthreads();

    for (int idx = t; idx < 4 * 512; idx += 256) {
        int g = idx >> 9, o = idx & 511;
        const float* wrow = &d1w[(pr[g] * 16) * 512 + o];
        float a = d1b[o];
#pragma unroll
        for (int k = 0; k < 16; k++) a += sel[g * 16 + k] * wrow[k * 512];
        r1s[idx] = fmaxf(a, 0.f);
    }
    __syncthreads();

#pragma unroll
    for (int c = 0; c < 2; c++) {
        int o1 = c * 512 + t, o2 = o1 + 256;
        float a[4][2];
#pragma unroll
        for (int g = 0; g < 4; g++) { a[g][0] = d2b[o1]; a[g][1] = d2b[o2]; }
        for (int k = 0; k < 512; k++) {
            float w1 = d2w[k * 1024 + o1];
            float w2 = d2w[k * 1024 + o2];
#pragma unroll
            for (int g = 0; g < 4; g++) {
                float r = r1s[g * 512 + k];
                a[g][0] += r * w1;
                a[g][1] += r * w2;
            }
        }
#pragma unroll
        for (int g = 0; g < 4; g++) {
            r2s[g * 1024 + o1] = fmaxf(a[g][0], 0.f);
            r2s[g * 1024 + o2] = fmaxf(a[g][1], 0.f);
        }
    }
    __syncthreads();

#pragma unroll
    for (int c = 0; c < 2; c++) {
        int o1 = c * 512 + t, o2 = o1 + 256;
        bool ok1 = o1 < 784, ok2 = o2 < 784;
        float a[4][2];
#pragma unroll
        for (int g = 0; g < 4; g++) {
            a[g][0] = ok1 ? d3b[o1] : 0.f;
            a[g][1] = ok2 ? d3b[o2] : 0.f;
        }
        for (int k = 0; k < 1024; k++) {
            float w1 = ok1 ? d3w[k * 784 + o1] : 0.f;
            float w2 = ok2 ? d3w[k * 784 + o2] : 0.f;
#pragma unroll
            for (int g = 0; g < 4; g++) {
                float r = r2s[g * 1024 + k];
                a[g][0] += r * w1;
                a[g][1] += r * w2;
            }
        }
#pragma unroll
        for (int g = 0; g < 4; g++) {
            if (ok1) out[RECON_OFF + (b0 + g) * 784 + o1] = 1.f / (1.f + expf(-a[g][0]));
            if (ok2) out[RECON_OFF + (b0 + g) * 784 + o2] = 1.f / (1.f + expf(-a[g][1]));
        }
    }
}

// ============================================================
extern "C" void kernel_launch(void* const* d_in, const int* in_sizes, int n_in,
                              void* d_out, int out_size) {
    const float* x   = (const float*)d_in[0];
    const float* c1w = (const float*)d_in[1];
    const float* c1b = (const float*)d_in[2];
    const float* c2w = (const float*)d_in[3];
    const float* c2b = (const float*)d_in[4];
    const float* W   = (const float*)d_in[5];
    const float* d1w = (const float*)d_in[6];
    const float* d1b = (const float*)d_in[7];
    const float* d2w = (const float*)d_in[8];
    const float* d2b = (const float*)d_in[9];
    const float* d3w = (const float*)d_in[10];
    const float* d3b = (const float*)d_in[11];
    float* out = (float*)d_out;

    cudaFuncSetAttribute(conv2_mma_kernel,
                         cudaFuncAttributeMaxDynamicSharedMemorySize, SMEM_BYTES);

    conv1_kernel<<<dim3(512, 16), 256>>>(x, c1w, c1b);
    repack_w2_kernel<<<(W2N + 255) / 256, 256>>>(c2w);
    conv2_mma_kernel<<<dim3(144, 4), 256, SMEM_BYTES>>>(c2b);
    usq_kernel<<<(BATCH * INCAPS + 255) / 256, 256>>>();
    uhat_kernel<<<INCAPS, 160>>>(W);
    routing_kernel<<<BATCH, 320>>>(out);
    decoder_kernel<<<BATCH / 4, 256>>>(d1w, d1b, d2w, d2b, d3w, d3b, out);
}